// round 16
// baseline (speedup 1.0000x reference)
#include <cuda_runtime.h>
#include <cuda_fp16.h>
#include <cstdint>

#define Cc 256
#define Ss 1024
#define Nn 32768
#define Dd 256
#define Kk 1024
#define OUT_LOSS 8388608
#define OUT_ENC  8388610

typedef unsigned long long u64;
typedef unsigned int u32;

// ---------------- device scratch (no allocations allowed) -------------------
__device__ __align__(16) __half gA[Nn * Dd];   // tokens, fp16
__device__ __align__(16) __half gB[Kk * Dd];   // codes,  fp16
__device__ float g_wnorm[Kk];
__device__ float g_xnorm[Nn];
__device__ float g_dmin[Nn];
__device__ int   g_idx[Nn];
__device__ int   g_cnt[Kk];
__device__ int   g_list[Nn];
__device__ int   g_nres;

// ---------------- helpers ----------------------------------------------------
__device__ __forceinline__ u32 smem_u32(const void* p){
  u32 a; asm("{ .reg .u64 t; cvta.to.shared.u64 t, %1; cvt.u32.u64 %0, t; }" : "=r"(a) : "l"(p));
  return a;
}
#define CP_ASYNC16(d, g) asm volatile("cp.async.cg.shared.global [%0], [%1], 16;" :: "r"(d), "l"(g))
#define CP_COMMIT()  asm volatile("cp.async.commit_group;" ::: "memory")
#define CP_WAIT1()   asm volatile("cp.async.wait_group 1;" ::: "memory")
#define CP_WAIT0()   asm volatile("cp.async.wait_group 0;" ::: "memory")

__device__ __forceinline__ void ldsm4(u32& a0, u32& a1, u32& a2, u32& a3, u32 addr){
  asm volatile("ldmatrix.sync.aligned.m8n8.x4.shared.b16 {%0,%1,%2,%3}, [%4];"
    : "=r"(a0), "=r"(a1), "=r"(a2), "=r"(a3) : "r"(addr));
}
__device__ __forceinline__ void mma16816(float* c, const u32* a, const u32* b){
  asm volatile("mma.sync.aligned.m16n8k16.row.col.f32.f16.f16.f32 "
    "{%0,%1,%2,%3}, {%4,%5,%6,%7}, {%8,%9}, {%0,%1,%2,%3};"
    : "+f"(c[0]), "+f"(c[1]), "+f"(c[2]), "+f"(c[3])
    : "r"(a[0]), "r"(a[1]), "r"(a[2]), "r"(a[3]), "r"(b[0]), "r"(b[1]));
}
__device__ __forceinline__ u32 ford(float v){
  u32 u = __float_as_uint(v);
  return (u & 0x80000000u) ? ~u : (u | 0x80000000u);
}
__device__ __forceinline__ float funord(u32 u){
  return __uint_as_float((u & 0x80000000u) ? (u & 0x7fffffffu) : ~u);
}
__device__ __forceinline__ u64 pack2(float lo, float hi){
  u64 r; asm("mov.b64 %0, {%1, %2};" : "=l"(r) : "f"(lo), "f"(hi)); return r;
}
__device__ __forceinline__ void unpack2(u64 v, float &lo, float &hi){
  asm("mov.b64 {%0, %1}, %2;" : "=f"(lo), "=f"(hi) : "l"(v));
}
__device__ __forceinline__ void fma2(u64 &d, u64 a, u64 b){
  asm("fma.rn.f32x2 %0, %1, %2, %0;" : "+l"(d) : "l"(a), "l"(b));
}
// packed fp32 add — REQUIRED for cross-lane reduction of packed accumulators
// (integer '+' on the packed u64 corrupts the floats: that was the R15 bug)
__device__ __forceinline__ u64 add2(u64 a, u64 b){
  u64 r; asm("add.rn.f32x2 %0, %1, %2;" : "=l"(r) : "l"(a), "l"(b)); return r;
}

// ---------------- prep kernels ----------------------------------------------
// codebook: norm + fp16 convert + zero counters. one warp per row, 128 blocks.
__global__ void vq_wprep(const float* __restrict__ W){
  int gid = blockIdx.x * 256 + threadIdx.x;
  if (gid < Kk) g_cnt[gid] = 0;
  if (gid == 0) g_nres = 0;
  int r = blockIdx.x * 8 + (threadIdx.x >> 5);
  int lane = threadIdx.x & 31;
  const float4* w4 = (const float4*)(W + r * Dd);
  float4 a = w4[lane], b = w4[lane + 32];
  float s = a.x*a.x + a.y*a.y + a.z*a.z + a.w*a.w
          + b.x*b.x + b.y*b.y + b.z*b.z + b.w*b.w;
  #pragma unroll
  for (int o = 16; o > 0; o >>= 1) s += __shfl_xor_sync(0xffffffffu, s, o);
  if (lane == 0) g_wnorm[r] = s;
  __half oa[4] = {__float2half(a.x), __float2half(a.y),
                  __float2half(a.z), __float2half(a.w)};
  __half ob[4] = {__float2half(b.x), __float2half(b.y),
                  __float2half(b.z), __float2half(b.w)};
  *(uint2*)(gB + r * Dd + lane * 4)       = *(uint2*)oa;
  *(uint2*)(gB + r * Dd + 128 + lane * 4) = *(uint2*)ob;
}

// tokens: BCHW transpose -> token-major fp16 + exact ||x||^2
__global__ __launch_bounds__(256) void vq_prep(const float* __restrict__ X){
  __shared__ float tile[Dd][33];
  __shared__ float pxn[8][32];
  int t = threadIdx.x, w = t >> 5, l = t & 31;
  int b = blockIdx.x >> 5, s0 = (blockIdx.x & 31) << 5;
  const float* Xp = X + b * (Dd * Ss) + s0 + l;
  float acc = 0.f;
  #pragma unroll
  for (int i = 0; i < 32; i++){
    int c = w + i * 8;
    float v = Xp[c * Ss];
    tile[c][l] = v; acc += v * v;
  }
  pxn[w][l] = acc;
  __syncthreads();
  if (t < 32){
    float s = 0.f;
    #pragma unroll
    for (int w2 = 0; w2 < 8; w2++) s += pxn[w2][t];
    g_xnorm[b * Ss + s0 + t] = s;
  }
  int tr = t >> 3, lane8 = t & 7;
  __half* dst = gA + (size_t)(b * Ss + s0 + tr) * Dd;
  #pragma unroll
  for (int i = 0; i < 4; i++){
    int cb = lane8 + i * 8;
    __half o[8];
    #pragma unroll
    for (int e = 0; e < 8; e++) o[e] = __float2half(tile[cb * 8 + e][tr]);
    *(uint4*)(dst + cb * 8) = *(uint4*)o;
  }
}

// ---------------- warp-MMA GEMM + fused top-2 argmin ------------------------
// 128 blocks x 256 tokens (single wave). A resident 128KB, B ring 3 x 16KB.
#define A_BYTES 131072
#define B_BYTES 16384
#define NBUF 3
#define SMEM_TOT (A_BYTES + NBUF * B_BYTES)

__device__ __forceinline__ void fillA(u32 ab, int n0, int t){
  const char* src = (const char*)gA + (size_t)n0 * (Dd * 2);
  #pragma unroll
  for (int j = 0; j < 16; j++){
    int idx = t + j * 512;
    int row = idx >> 5, c = idx & 31;
    u32 dst = ab + (u32)(row * 512) + (u32)((c ^ (row & 7)) << 4);
    CP_ASYNC16(dst, src + (size_t)row * 512 + c * 16);
  }
}
__device__ __forceinline__ void fillB(u32 bb, int nc, int kc, int t){
  const char* src = (const char*)gB + (size_t)(nc * 128) * 512 + (size_t)kc * 128;
  #pragma unroll
  for (int j = 0; j < 2; j++){
    int idx = t + j * 512;
    int n = idx >> 3, c = idx & 7;
    u32 dst = bb + (u32)(n * 128) + (u32)((c ^ (n & 7)) << 4);
    CP_ASYNC16(dst, src + (size_t)n * 512 + c * 16);
  }
}

__global__ __launch_bounds__(512, 1) void vq_gemm_tc(){
  extern __shared__ __align__(16) char dsm[];
  const u32 dbase = smem_u32(dsm);
  const int t = threadIdx.x, lane = t & 31, w = t >> 5;
  const int wm = w & 7, wn = w >> 3;     // 8x2 warp grid: 32 tok x 64 codes / warp
  const int n0 = blockIdx.x * 256;

  const int arow = wm * 32 + (lane & 15);                       // + mt*16
  const int bnb  = wn * 64 + ((lane >> 4) << 3) + (lane & 7);   // + ntp*16

  float t1[4], t2[4]; int ti[4];
  #pragma unroll
  for (int i = 0; i < 4; i++){ t1[i] = 3.4e38f; t2[i] = 3.4e38f; ti[i] = 0; }

  fillA(dbase, n0, t);               CP_COMMIT();
  fillB(dbase + A_BYTES, 0, 0, t);   CP_COMMIT();
  fillB(dbase + A_BYTES + B_BYTES, 0, 1, t); CP_COMMIT();

  float acc[2][8][4];
  for (int g = 0; g < 32; g++){
    const int nc = g >> 2, kc = g & 3;
    if (kc == 0){
      #pragma unroll
      for (int mt = 0; mt < 2; mt++)
        #pragma unroll
        for (int nt = 0; nt < 8; nt++)
          #pragma unroll
          for (int q = 0; q < 4; q++) acc[mt][nt][q] = 0.f;
    }
    if (g < 31) CP_WAIT1(); else CP_WAIT0();
    __syncthreads();
    if (g + 2 < 32){
      int g2 = g + 2;
      fillB(dbase + A_BYTES + (u32)((g2 % NBUF) * B_BYTES), g2 >> 2, g2 & 3, t);
      CP_COMMIT();
    }

    const u32 bb = dbase + A_BYTES + (u32)((g % NBUF) * B_BYTES);
    #pragma unroll
    for (int ks = 0; ks < 4; ks++){
      u32 afr[2][4];
      int ca = kc * 8 + ks * 2 + (lane >> 4);
      #pragma unroll
      for (int mt = 0; mt < 2; mt++){
        int r = arow + mt * 16;
        u32 ad = dbase + (u32)(r * 512) + (u32)((ca ^ (r & 7)) << 4);
        ldsm4(afr[mt][0], afr[mt][1], afr[mt][2], afr[mt][3], ad);
      }
      u32 bfr[8][2];
      int ckl = ks * 2 + ((lane >> 3) & 1);
      #pragma unroll
      for (int ntp = 0; ntp < 4; ntp++){
        int n = bnb + ntp * 16;
        u32 bd = bb + (u32)(n * 128) + (u32)((ckl ^ (n & 7)) << 4);
        ldsm4(bfr[2*ntp][0], bfr[2*ntp][1], bfr[2*ntp+1][0], bfr[2*ntp+1][1], bd);
      }
      #pragma unroll
      for (int mt = 0; mt < 2; mt++)
        #pragma unroll
        for (int nt = 0; nt < 8; nt++)
          mma16816(acc[mt][nt], afr[mt], bfr[nt]);
    }

    if (kc == 3){
      int cb0 = nc * 128 + wn * 64 + (lane & 3) * 2;
      #pragma unroll
      for (int nt = 0; nt < 8; nt++){
        int c0 = cb0 + nt * 8;
        float w0 = __ldg(&g_wnorm[c0]), w1 = __ldg(&g_wnorm[c0 + 1]);
        #pragma unroll
        for (int mt = 0; mt < 2; mt++)
          #pragma unroll
          for (int h = 0; h < 2; h++){
            int s = mt * 2 + h;
            float d0 = fmaf(-2.0f, acc[mt][nt][h*2+0], w0);
            float d1 = fmaf(-2.0f, acc[mt][nt][h*2+1], w1);
            if (d0 < t1[s]){ t2[s] = t1[s]; t1[s] = d0; ti[s] = c0; }
            else if (d0 < t2[s]) t2[s] = d0;
            if (d1 < t1[s]){ t2[s] = t1[s]; t1[s] = d1; ti[s] = c0 + 1; }
            else if (d1 < t2[s]) t2[s] = d1;
          }
      }
    }
  }

  // merge the 4 lanes sharing each token row
  u64 key[4];
  #pragma unroll
  for (int s = 0; s < 4; s++) key[s] = ((u64)ford(t1[s]) << 32) | (u32)ti[s];
  #pragma unroll
  for (int off = 1; off <= 2; off <<= 1){
    #pragma unroll
    for (int s = 0; s < 4; s++){
      u64 ko  = __shfl_xor_sync(0xffffffffu, key[s], off);
      float mo = __shfl_xor_sync(0xffffffffu, t2[s], off);
      float va = funord((u32)(key[s] >> 32));
      float vb = funord((u32)(ko >> 32));
      t2[s] = fminf(fminf(t2[s], mo), fmaxf(va, vb));
      if (ko < key[s]) key[s] = ko;
    }
  }
  __syncthreads();  // B ring dead; reuse as reduce scratch
  u64*   sm1 = (u64*)(dsm + A_BYTES);            // [2][256]
  float* sm2 = (float*)(dsm + A_BYTES + 8192);   // [2][256]
  if ((lane & 3) == 0){
    #pragma unroll
    for (int s = 0; s < 4; s++){
      int mt = s >> 1, h = s & 1;
      int row = wm * 32 + mt * 16 + (lane >> 2) + h * 8;
      sm1[wn * 256 + row] = key[s];
      sm2[wn * 256 + row] = t2[s];
    }
  }
  __syncthreads();
  if (t < 256){
    u64 bk = sm1[t];          float m2 = sm2[t];
    u64 k2 = sm1[256 + t];    float mm = sm2[256 + t];
    float va = funord((u32)(bk >> 32));
    float vb = funord((u32)(k2 >> 32));
    m2 = fminf(fminf(m2, mm), fmaxf(va, vb));
    if (k2 < bk) bk = k2;
    int tok = n0 + t;
    float d1 = funord((u32)(bk >> 32));
    g_idx[tok]  = (int)(bk & 0xffffffffu);
    g_dmin[tok] = g_xnorm[tok] + d1;
    if (m2 - d1 < 0.25f){                // fp16 distance err max ~4.5e-2
      int p = atomicAdd(&g_nres, 1);
      g_list[p] = tok;
    }
  }
}

// ---------------- exact fp32 rescue ------------------------------------------
// 4 tokens/group -> ~nres/4 active blocks (full chip at nres ~600+).
// Thread (c = t>>3, q = t&7): code row c of each 32-code tile, dim-slice q*32.
// W slice loaded straight to registers (coalesced per warp), tokens in tiny
// conflict-free smem. Chain length 32; no syncthreads inside the tile loop.
__global__ __launch_bounds__(256, 1) void vq_rescue(const float* __restrict__ X,
                                                    const float* __restrict__ W){
  __shared__ __align__(8) float xs[2][8][33][2];   // [pair][slice][dim][slot]
  __shared__ u64 red[4];
  const int t = threadIdx.x;
  const int c = t >> 3, q = t & 7;
  const int nr = g_nres;

  for (int base = blockIdx.x * 4; base < nr; base += gridDim.x * 4){
    int cnt = min(4, nr - base);
    __syncthreads();           // protect xs/red from previous iteration's readers
    for (int i = t; i < 4 * Dd; i += 256){
      int j = i >> 8, d = i & 255;
      float v = 0.f;
      if (j < cnt){
        int tok = g_list[base + j];
        v = X[(tok >> 10) * (Dd * Ss) + d * Ss + (tok & 1023)];
      }
      // pair p=j&1: slot0 = token p, slot1 = token p+2
      xs[j & 1][d >> 5][d & 31][j >> 1] = v;
    }
    if (t < 4) red[t] = 0xFFFFFFFFFFFFFFFFull;
    __syncthreads();

    u64 best[4] = {0xFFFFFFFFFFFFFFFFull, 0xFFFFFFFFFFFFFFFFull,
                   0xFFFFFFFFFFFFFFFFull, 0xFFFFFFFFFFFFFFFFull};

    #pragma unroll 1
    for (int tile = 0; tile < 32; tile++){
      int k = tile * 32 + c;
      const float* wr = W + (size_t)k * Dd + q * 32;
      float4 wv[8];
      #pragma unroll
      for (int i = 0; i < 8; i++) wv[i] = *(const float4*)(wr + i * 4);

      u64 a0 = 0ull, a1 = 0ull;
      #pragma unroll
      for (int i = 0; i < 8; i++){
        #pragma unroll
        for (int e = 0; e < 4; e++){
          int dd = i * 4 + e;
          float wf = ((const float*)&wv[i])[e];
          u64 w2 = pack2(wf, wf);
          fma2(a0, *(const u64*)&xs[0][q][dd][0], w2);
          fma2(a1, *(const u64*)&xs[1][q][dd][0], w2);
        }
      }
      // reduce over the 8 dim-slices (8-lane groups) with PACKED-FLOAT adds
      #pragma unroll
      for (int off = 1; off <= 4; off <<= 1){
        a0 = add2(a0, __shfl_xor_sync(0xffffffffu, a0, off));
        a1 = add2(a1, __shfl_xor_sync(0xffffffffu, a1, off));
      }
      if (q == 0){
        float wn = g_wnorm[k];
        float d0, d2, d1, d3;
        unpack2(a0, d0, d2);   // pair0 = tokens 0,2
        unpack2(a1, d1, d3);   // pair1 = tokens 1,3
        u64 kk;
        kk = ((u64)ford(fmaf(-2.f, d0, wn)) << 32) | (u32)k; if (kk < best[0]) best[0] = kk;
        kk = ((u64)ford(fmaf(-2.f, d1, wn)) << 32) | (u32)k; if (kk < best[1]) best[1] = kk;
        kk = ((u64)ford(fmaf(-2.f, d2, wn)) << 32) | (u32)k; if (kk < best[2]) best[2] = kk;
        kk = ((u64)ford(fmaf(-2.f, d3, wn)) << 32) | (u32)k; if (kk < best[3]) best[3] = kk;
      }
    }

    if (q == 0){
      atomicMin(&red[0], best[0]);   // token 0
      atomicMin(&red[1], best[1]);   // token 1
      atomicMin(&red[2], best[2]);   // token 2
      atomicMin(&red[3], best[3]);   // token 3
    }
    __syncthreads();
    if (t < cnt){
      u64 kk = red[t];
      int tok = g_list[base + t];
      g_idx[tok]  = (int)(kk & 0xffffffffu);
      g_dmin[tok] = g_xnorm[tok] + funord((u32)(kk >> 32));
    }
  }
}

// quantized output in BCHW
__global__ void vq_gather(const float* __restrict__ W, float* __restrict__ out){
  int g   = blockIdx.x * 256 + threadIdx.x;
  int c4  = g >> 15;
  int rem = g & 32767;
  int b = rem >> 10, s = rem & 1023;
  int id = g_idx[rem];
  float4 w = *(const float4*)(W + id * Dd + c4 * 4);
  float* o = out + b * (Cc * Ss) + (c4 * 4) * Ss + s;
  o[0] = w.x; o[Ss] = w.y; o[2*Ss] = w.z; o[3*Ss] = w.w;
}

// one-hot encodings + histogram fused.
// float2 ONLY: enc base = d_out + 8388610 floats => 8B-aligned, NOT 16B.
__global__ void vq_enc(float* __restrict__ enc){
  int g  = blockIdx.x * 256 + threadIdx.x;    // Nn*Kk/2 threads
  int n  = g >> 9;
  int k2 = (g & 511) * 2;
  int id = g_idx[n];
  float2 v;
  v.x = (id == k2    ) ? 1.0f : 0.0f;
  v.y = (id == k2 + 1) ? 1.0f : 0.0f;
  if ((unsigned)(id - k2) < 2u) atomicAdd(&g_cnt[id], 1);
  *(float2*)(enc + (size_t)n * Kk + k2) = v;
}

__global__ void vq_final(float* __restrict__ scal){
  __shared__ float sh[1024];
  int t = threadIdx.x;
  float s = 0.0f;
  for (int i = t; i < Nn; i += 1024) s += g_dmin[i];
  sh[t] = s; __syncthreads();
  for (int o = 512; o > 0; o >>= 1){ if (t < o) sh[t] += sh[t + o]; __syncthreads(); }
  float losssum = sh[0];
  __syncthreads();
  float p = (float)g_cnt[t] * (1.0f / (float)Nn);
  sh[t] = -p * logf(p + 1e-10f);
  __syncthreads();
  for (int o = 512; o > 0; o >>= 1){ if (t < o) sh[t] += sh[t + o]; __syncthreads(); }
  if (t == 0){
    scal[0] = 0.25f * losssum / (float)(Nn * Dd);
    scal[1] = sh[0];
  }
}

// ---------------- launch -----------------------------------------------------
extern "C" void kernel_launch(void* const* d_in, const int* in_sizes, int n_in,
                              void* d_out, int out_size){
  (void)in_sizes; (void)n_in; (void)out_size;
  const float* X = (const float*)d_in[0];
  const float* W = (const float*)d_in[1];
  float* out = (float*)d_out;

  cudaFuncSetAttribute(vq_gemm_tc, cudaFuncAttributeMaxDynamicSharedMemorySize, SMEM_TOT);

  vq_wprep  <<<Kk / 8, 256>>>(W);
  vq_prep   <<<1024, 256>>>(X);
  vq_gemm_tc<<<Nn / 256, 512, SMEM_TOT>>>();
  vq_rescue <<<256, 256>>>(X, W);
  vq_gather <<<(Nn * Dd / 4) / 256, 256>>>(W, out);
  vq_enc    <<<(Nn * (Kk / 2)) / 256, 256>>>(out + OUT_ENC);
  vq_final  <<<1, Kk>>>(out + OUT_LOSS);
}

// round 17
// speedup vs baseline: 1.7015x; 1.7015x over previous
#include <cuda_runtime.h>
#include <cuda_fp16.h>
#include <cstdint>

#define Cc 256
#define Ss 1024
#define Nn 32768
#define Dd 256
#define Kk 1024
#define OUT_LOSS 8388608
#define OUT_ENC  8388610

typedef unsigned long long u64;
typedef unsigned int u32;

// ---------------- device scratch (no allocations allowed) -------------------
__device__ __align__(16) __half gA[Nn * Dd];   // tokens, fp16
__device__ __align__(16) __half gB[Kk * Dd];   // codes,  fp16
__device__ float g_wnorm[Kk];
__device__ float g_xnorm[Nn];
__device__ float g_dmin[Nn];
__device__ int   g_idx[Nn];
__device__ int   g_cnt[Kk];
__device__ int   g_list[Nn];
__device__ int   g_nres;

// ---------------- helpers ----------------------------------------------------
__device__ __forceinline__ u32 smem_u32(const void* p){
  u32 a; asm("{ .reg .u64 t; cvta.to.shared.u64 t, %1; cvt.u32.u64 %0, t; }" : "=r"(a) : "l"(p));
  return a;
}
#define CP_ASYNC16(d, g) asm volatile("cp.async.cg.shared.global [%0], [%1], 16;" :: "r"(d), "l"(g))
#define CP_COMMIT()  asm volatile("cp.async.commit_group;" ::: "memory")
#define CP_WAIT1()   asm volatile("cp.async.wait_group 1;" ::: "memory")
#define CP_WAIT0()   asm volatile("cp.async.wait_group 0;" ::: "memory")

__device__ __forceinline__ void ldsm4(u32& a0, u32& a1, u32& a2, u32& a3, u32 addr){
  asm volatile("ldmatrix.sync.aligned.m8n8.x4.shared.b16 {%0,%1,%2,%3}, [%4];"
    : "=r"(a0), "=r"(a1), "=r"(a2), "=r"(a3) : "r"(addr));
}
__device__ __forceinline__ void mma16816(float* c, const u32* a, const u32* b){
  asm volatile("mma.sync.aligned.m16n8k16.row.col.f32.f16.f16.f32 "
    "{%0,%1,%2,%3}, {%4,%5,%6,%7}, {%8,%9}, {%0,%1,%2,%3};"
    : "+f"(c[0]), "+f"(c[1]), "+f"(c[2]), "+f"(c[3])
    : "r"(a[0]), "r"(a[1]), "r"(a[2]), "r"(a[3]), "r"(b[0]), "r"(b[1]));
}
__device__ __forceinline__ u32 ford(float v){
  u32 u = __float_as_uint(v);
  return (u & 0x80000000u) ? ~u : (u | 0x80000000u);
}
__device__ __forceinline__ float funord(u32 u){
  return __uint_as_float((u & 0x80000000u) ? (u & 0x7fffffffu) : ~u);
}
__device__ __forceinline__ u64 pack2(float lo, float hi){
  u64 r; asm("mov.b64 %0, {%1, %2};" : "=l"(r) : "f"(lo), "f"(hi)); return r;
}
__device__ __forceinline__ void unpack2(u64 v, float &lo, float &hi){
  asm("mov.b64 {%0, %1}, %2;" : "=f"(lo), "=f"(hi) : "l"(v));
}
__device__ __forceinline__ void fma2(u64 &d, u64 a, u64 b){
  asm("fma.rn.f32x2 %0, %1, %2, %0;" : "+l"(d) : "l"(a), "l"(b));
}
// packed fp32 add — cross-lane reduction of packed accumulators must use this
// (integer '+' on the packed u64 corrupts the floats: R15 bug)
__device__ __forceinline__ u64 add2(u64 a, u64 b){
  u64 r; asm("add.rn.f32x2 %0, %1, %2;" : "=l"(r) : "l"(a), "l"(b)); return r;
}

// ---------------- prep kernels ----------------------------------------------
// codebook: norm + fp16 convert + zero counters. one warp per row, 128 blocks.
__global__ void vq_wprep(const float* __restrict__ W){
  int gid = blockIdx.x * 256 + threadIdx.x;
  if (gid < Kk) g_cnt[gid] = 0;
  if (gid == 0) g_nres = 0;
  int r = blockIdx.x * 8 + (threadIdx.x >> 5);
  int lane = threadIdx.x & 31;
  const float4* w4 = (const float4*)(W + r * Dd);
  float4 a = w4[lane], b = w4[lane + 32];
  float s = a.x*a.x + a.y*a.y + a.z*a.z + a.w*a.w
          + b.x*b.x + b.y*b.y + b.z*b.z + b.w*b.w;
  #pragma unroll
  for (int o = 16; o > 0; o >>= 1) s += __shfl_xor_sync(0xffffffffu, s, o);
  if (lane == 0) g_wnorm[r] = s;
  __half oa[4] = {__float2half(a.x), __float2half(a.y),
                  __float2half(a.z), __float2half(a.w)};
  __half ob[4] = {__float2half(b.x), __float2half(b.y),
                  __float2half(b.z), __float2half(b.w)};
  *(uint2*)(gB + r * Dd + lane * 4)       = *(uint2*)oa;
  *(uint2*)(gB + r * Dd + 128 + lane * 4) = *(uint2*)ob;
}

// tokens: BCHW transpose -> token-major fp16 + exact ||x||^2
__global__ __launch_bounds__(256) void vq_prep(const float* __restrict__ X){
  __shared__ float tile[Dd][33];
  __shared__ float pxn[8][32];
  int t = threadIdx.x, w = t >> 5, l = t & 31;
  int b = blockIdx.x >> 5, s0 = (blockIdx.x & 31) << 5;
  const float* Xp = X + b * (Dd * Ss) + s0 + l;
  float acc = 0.f;
  #pragma unroll
  for (int i = 0; i < 32; i++){
    int c = w + i * 8;
    float v = Xp[c * Ss];
    tile[c][l] = v; acc += v * v;
  }
  pxn[w][l] = acc;
  __syncthreads();
  if (t < 32){
    float s = 0.f;
    #pragma unroll
    for (int w2 = 0; w2 < 8; w2++) s += pxn[w2][t];
    g_xnorm[b * Ss + s0 + t] = s;
  }
  int tr = t >> 3, lane8 = t & 7;
  __half* dst = gA + (size_t)(b * Ss + s0 + tr) * Dd;
  #pragma unroll
  for (int i = 0; i < 4; i++){
    int cb = lane8 + i * 8;
    __half o[8];
    #pragma unroll
    for (int e = 0; e < 8; e++) o[e] = __float2half(tile[cb * 8 + e][tr]);
    *(uint4*)(dst + cb * 8) = *(uint4*)o;
  }
}

// ---------------- warp-MMA GEMM + fused top-2 argmin ------------------------
// 128 blocks x 256 tokens (single wave). A resident 128KB, B ring 3 x 16KB.
#define A_BYTES 131072
#define B_BYTES 16384
#define NBUF 3
#define SMEM_TOT (A_BYTES + NBUF * B_BYTES)

__device__ __forceinline__ void fillA(u32 ab, int n0, int t){
  const char* src = (const char*)gA + (size_t)n0 * (Dd * 2);
  #pragma unroll
  for (int j = 0; j < 16; j++){
    int idx = t + j * 512;
    int row = idx >> 5, c = idx & 31;
    u32 dst = ab + (u32)(row * 512) + (u32)((c ^ (row & 7)) << 4);
    CP_ASYNC16(dst, src + (size_t)row * 512 + c * 16);
  }
}
__device__ __forceinline__ void fillB(u32 bb, int nc, int kc, int t){
  const char* src = (const char*)gB + (size_t)(nc * 128) * 512 + (size_t)kc * 128;
  #pragma unroll
  for (int j = 0; j < 2; j++){
    int idx = t + j * 512;
    int n = idx >> 3, c = idx & 7;
    u32 dst = bb + (u32)(n * 128) + (u32)((c ^ (n & 7)) << 4);
    CP_ASYNC16(dst, src + (size_t)n * 512 + c * 16);
  }
}

__global__ __launch_bounds__(512, 1) void vq_gemm_tc(){
  extern __shared__ __align__(16) char dsm[];
  const u32 dbase = smem_u32(dsm);
  const int t = threadIdx.x, lane = t & 31, w = t >> 5;
  const int wm = w & 7, wn = w >> 3;     // 8x2 warp grid: 32 tok x 64 codes / warp
  const int n0 = blockIdx.x * 256;

  const int arow = wm * 32 + (lane & 15);                       // + mt*16
  const int bnb  = wn * 64 + ((lane >> 4) << 3) + (lane & 7);   // + ntp*16

  float t1[4], t2[4]; int ti[4];
  #pragma unroll
  for (int i = 0; i < 4; i++){ t1[i] = 3.4e38f; t2[i] = 3.4e38f; ti[i] = 0; }

  fillA(dbase, n0, t);               CP_COMMIT();
  fillB(dbase + A_BYTES, 0, 0, t);   CP_COMMIT();
  fillB(dbase + A_BYTES + B_BYTES, 0, 1, t); CP_COMMIT();

  float acc[2][8][4];
  for (int g = 0; g < 32; g++){
    const int nc = g >> 2, kc = g & 3;
    if (kc == 0){
      #pragma unroll
      for (int mt = 0; mt < 2; mt++)
        #pragma unroll
        for (int nt = 0; nt < 8; nt++)
          #pragma unroll
          for (int q = 0; q < 4; q++) acc[mt][nt][q] = 0.f;
    }
    if (g < 31) CP_WAIT1(); else CP_WAIT0();
    __syncthreads();
    if (g + 2 < 32){
      int g2 = g + 2;
      fillB(dbase + A_BYTES + (u32)((g2 % NBUF) * B_BYTES), g2 >> 2, g2 & 3, t);
      CP_COMMIT();
    }

    const u32 bb = dbase + A_BYTES + (u32)((g % NBUF) * B_BYTES);
    #pragma unroll
    for (int ks = 0; ks < 4; ks++){
      u32 afr[2][4];
      int ca = kc * 8 + ks * 2 + (lane >> 4);
      #pragma unroll
      for (int mt = 0; mt < 2; mt++){
        int r = arow + mt * 16;
        u32 ad = dbase + (u32)(r * 512) + (u32)((ca ^ (r & 7)) << 4);
        ldsm4(afr[mt][0], afr[mt][1], afr[mt][2], afr[mt][3], ad);
      }
      u32 bfr[8][2];
      int ckl = ks * 2 + ((lane >> 3) & 1);
      #pragma unroll
      for (int ntp = 0; ntp < 4; ntp++){
        int n = bnb + ntp * 16;
        u32 bd = bb + (u32)(n * 128) + (u32)((ckl ^ (n & 7)) << 4);
        ldsm4(bfr[2*ntp][0], bfr[2*ntp][1], bfr[2*ntp+1][0], bfr[2*ntp+1][1], bd);
      }
      #pragma unroll
      for (int mt = 0; mt < 2; mt++)
        #pragma unroll
        for (int nt = 0; nt < 8; nt++)
          mma16816(acc[mt][nt], afr[mt], bfr[nt]);
    }

    if (kc == 3){
      int cb0 = nc * 128 + wn * 64 + (lane & 3) * 2;
      #pragma unroll
      for (int nt = 0; nt < 8; nt++){
        int c0 = cb0 + nt * 8;
        float w0 = __ldg(&g_wnorm[c0]), w1 = __ldg(&g_wnorm[c0 + 1]);
        #pragma unroll
        for (int mt = 0; mt < 2; mt++)
          #pragma unroll
          for (int h = 0; h < 2; h++){
            int s = mt * 2 + h;
            float d0 = fmaf(-2.0f, acc[mt][nt][h*2+0], w0);
            float d1 = fmaf(-2.0f, acc[mt][nt][h*2+1], w1);
            if (d0 < t1[s]){ t2[s] = t1[s]; t1[s] = d0; ti[s] = c0; }
            else if (d0 < t2[s]) t2[s] = d0;
            if (d1 < t1[s]){ t2[s] = t1[s]; t1[s] = d1; ti[s] = c0 + 1; }
            else if (d1 < t2[s]) t2[s] = d1;
          }
      }
    }
  }

  // merge the 4 lanes sharing each token row
  u64 key[4];
  #pragma unroll
  for (int s = 0; s < 4; s++) key[s] = ((u64)ford(t1[s]) << 32) | (u32)ti[s];
  #pragma unroll
  for (int off = 1; off <= 2; off <<= 1){
    #pragma unroll
    for (int s = 0; s < 4; s++){
      u64 ko  = __shfl_xor_sync(0xffffffffu, key[s], off);
      float mo = __shfl_xor_sync(0xffffffffu, t2[s], off);
      float va = funord((u32)(key[s] >> 32));
      float vb = funord((u32)(ko >> 32));
      t2[s] = fminf(fminf(t2[s], mo), fmaxf(va, vb));
      if (ko < key[s]) key[s] = ko;
    }
  }
  __syncthreads();  // B ring dead; reuse as reduce scratch
  u64*   sm1 = (u64*)(dsm + A_BYTES);            // [2][256]
  float* sm2 = (float*)(dsm + A_BYTES + 8192);   // [2][256]
  if ((lane & 3) == 0){
    #pragma unroll
    for (int s = 0; s < 4; s++){
      int mt = s >> 1, h = s & 1;
      int row = wm * 32 + mt * 16 + (lane >> 2) + h * 8;
      sm1[wn * 256 + row] = key[s];
      sm2[wn * 256 + row] = t2[s];
    }
  }
  __syncthreads();
  if (t < 256){
    u64 bk = sm1[t];          float m2 = sm2[t];
    u64 k2 = sm1[256 + t];    float mm = sm2[256 + t];
    float va = funord((u32)(bk >> 32));
    float vb = funord((u32)(k2 >> 32));
    m2 = fminf(fminf(m2, mm), fmaxf(va, vb));
    if (k2 < bk) bk = k2;
    int tok = n0 + t;
    float d1 = funord((u32)(bk >> 32));
    g_idx[tok]  = (int)(bk & 0xffffffffu);
    g_dmin[tok] = g_xnorm[tok] + d1;
    if (m2 - d1 < 0.25f){                // fp16 distance err max ~4.5e-2
      int p = atomicAdd(&g_nres, 1);
      g_list[p] = tok;
    }
  }
}

// ---------------- exact fp32 rescue ------------------------------------------
// 4 tokens/group. Per 32-code tile the BLOCK cooperatively stages the 32KB W
// tile into smem with fully-coalesced float4 LDGs (R16 had each warp issuing
// 32-line uncoalesced LDGs, 8x redundant -> L1tex-bound at 178us).
// smem layout: 256 slots (slot = c*8+q) of 32 floats, pad 33 -> reads bank
// = slot+dd (distinct/warp), scatter-writes bank = 8c+q+dd (distinct/warp).
// Compute path identical to R16 (fma2 pairs + add2/shfl reduce).
__global__ __launch_bounds__(256, 1) void vq_rescue(const float* __restrict__ X,
                                                    const float* __restrict__ W){
  __shared__ __align__(8) float xs[2][8][33][2];   // [pair][slice][dim][slot]
  __shared__ float ws[256 * 33];                   // 256 slots x 32 floats (pad 33)
  __shared__ u64 red[4];
  const int t = threadIdx.x;
  const int c = t >> 3, q = t & 7;
  const int nr = g_nres;

  for (int base = blockIdx.x * 4; base < nr; base += gridDim.x * 4){
    int cnt = min(4, nr - base);
    __syncthreads();           // protect xs/red from previous iteration's readers
    for (int i = t; i < 4 * Dd; i += 256){
      int j = i >> 8, d = i & 255;
      float v = 0.f;
      if (j < cnt){
        int tok = g_list[base + j];
        v = X[(tok >> 10) * (Dd * Ss) + d * Ss + (tok & 1023)];
      }
      // pair p=j&1: slot0 = token p, slot1 = token p+2
      xs[j & 1][d >> 5][d & 31][j >> 1] = v;
    }
    if (t < 4) red[t] = 0xFFFFFFFFFFFFFFFFull;
    __syncthreads();

    u64 best[4] = {0xFFFFFFFFFFFFFFFFull, 0xFFFFFFFFFFFFFFFFull,
                   0xFFFFFFFFFFFFFFFFull, 0xFFFFFFFFFFFFFFFFull};

    #pragma unroll 1
    for (int tile = 0; tile < 32; tile++){
      // cooperative coalesced W tile load: 32 codes x 256 dims = 8192 floats
      #pragma unroll
      for (int j = 0; j < 8; j++){
        int fidx = t + j * 256;                 // float4 index 0..2047
        float4 v = *(const float4*)(W + (size_t)tile * 8192 + (size_t)fidx * 4);
        int g4  = fidx * 4;
        int cc  = g4 >> 8;                      // code row 0..31
        int col = g4 & 255;
        float* p = &ws[(cc * 8 + (col >> 5)) * 33 + (col & 31)];
        p[0] = v.x; p[1] = v.y; p[2] = v.z; p[3] = v.w;
      }
      __syncthreads();

      int k = tile * 32 + c;
      const float* wrow = &ws[(c * 8 + q) * 33];
      u64 a0 = 0ull, a1 = 0ull;
      #pragma unroll
      for (int dd = 0; dd < 32; dd++){
        float wf = wrow[dd];
        u64 w2 = pack2(wf, wf);
        fma2(a0, *(const u64*)&xs[0][q][dd][0], w2);
        fma2(a1, *(const u64*)&xs[1][q][dd][0], w2);
      }
      // reduce over the 8 dim-slices (8-lane groups) with PACKED-FLOAT adds
      #pragma unroll
      for (int off = 1; off <= 4; off <<= 1){
        a0 = add2(a0, __shfl_xor_sync(0xffffffffu, a0, off));
        a1 = add2(a1, __shfl_xor_sync(0xffffffffu, a1, off));
      }
      if (q == 0){
        float wn = g_wnorm[k];
        float d0, d2, d1, d3;
        unpack2(a0, d0, d2);   // pair0 = tokens 0,2
        unpack2(a1, d1, d3);   // pair1 = tokens 1,3
        u64 kk;
        kk = ((u64)ford(fmaf(-2.f, d0, wn)) << 32) | (u32)k; if (kk < best[0]) best[0] = kk;
        kk = ((u64)ford(fmaf(-2.f, d1, wn)) << 32) | (u32)k; if (kk < best[1]) best[1] = kk;
        kk = ((u64)ford(fmaf(-2.f, d2, wn)) << 32) | (u32)k; if (kk < best[2]) best[2] = kk;
        kk = ((u64)ford(fmaf(-2.f, d3, wn)) << 32) | (u32)k; if (kk < best[3]) best[3] = kk;
      }
      __syncthreads();         // ws consumed; safe to overwrite next tile
    }

    if (q == 0){
      atomicMin(&red[0], best[0]);   // token 0
      atomicMin(&red[1], best[1]);   // token 1
      atomicMin(&red[2], best[2]);   // token 2
      atomicMin(&red[3], best[3]);   // token 3
    }
    __syncthreads();
    if (t < cnt){
      u64 kk = red[t];
      int tok = g_list[base + t];
      g_idx[tok]  = (int)(kk & 0xffffffffu);
      g_dmin[tok] = g_xnorm[tok] + funord((u32)(kk >> 32));
    }
  }
}

// quantized output in BCHW
__global__ void vq_gather(const float* __restrict__ W, float* __restrict__ out){
  int g   = blockIdx.x * 256 + threadIdx.x;
  int c4  = g >> 15;
  int rem = g & 32767;
  int b = rem >> 10, s = rem & 1023;
  int id = g_idx[rem];
  float4 w = *(const float4*)(W + id * Dd + c4 * 4);
  float* o = out + b * (Cc * Ss) + (c4 * 4) * Ss + s;
  o[0] = w.x; o[Ss] = w.y; o[2*Ss] = w.z; o[3*Ss] = w.w;
}

// one-hot encodings + histogram fused.
// float2 ONLY: enc base = d_out + 8388610 floats => 8B-aligned, NOT 16B.
__global__ void vq_enc(float* __restrict__ enc){
  int g  = blockIdx.x * 256 + threadIdx.x;    // Nn*Kk/2 threads
  int n  = g >> 9;
  int k2 = (g & 511) * 2;
  int id = g_idx[n];
  float2 v;
  v.x = (id == k2    ) ? 1.0f : 0.0f;
  v.y = (id == k2 + 1) ? 1.0f : 0.0f;
  if ((unsigned)(id - k2) < 2u) atomicAdd(&g_cnt[id], 1);
  *(float2*)(enc + (size_t)n * Kk + k2) = v;
}

__global__ void vq_final(float* __restrict__ scal){
  __shared__ float sh[1024];
  int t = threadIdx.x;
  float s = 0.0f;
  for (int i = t; i < Nn; i += 1024) s += g_dmin[i];
  sh[t] = s; __syncthreads();
  for (int o = 512; o > 0; o >>= 1){ if (t < o) sh[t] += sh[t + o]; __syncthreads(); }
  float losssum = sh[0];
  __syncthreads();
  float p = (float)g_cnt[t] * (1.0f / (float)Nn);
  sh[t] = -p * logf(p + 1e-10f);
  __syncthreads();
  for (int o = 512; o > 0; o >>= 1){ if (t < o) sh[t] += sh[t + o]; __syncthreads(); }
  if (t == 0){
    scal[0] = 0.25f * losssum / (float)(Nn * Dd);
    scal[1] = sh[0];
  }
}

// ---------------- launch -----------------------------------------------------
extern "C" void kernel_launch(void* const* d_in, const int* in_sizes, int n_in,
                              void* d_out, int out_size){
  (void)in_sizes; (void)n_in; (void)out_size;
  const float* X = (const float*)d_in[0];
  const float* W = (const float*)d_in[1];
  float* out = (float*)d_out;

  cudaFuncSetAttribute(vq_gemm_tc, cudaFuncAttributeMaxDynamicSharedMemorySize, SMEM_TOT);

  vq_wprep  <<<Kk / 8, 256>>>(W);
  vq_prep   <<<1024, 256>>>(X);
  vq_gemm_tc<<<Nn / 256, 512, SMEM_TOT>>>();
  vq_rescue <<<256, 256>>>(X, W);
  vq_gather <<<(Nn * Dd / 4) / 256, 256>>>(W, out);
  vq_enc    <<<(Nn * (Kk / 2)) / 256, 256>>>(out + OUT_ENC);
  vq_final  <<<1, Kk>>>(out + OUT_LOSS);
}